// round 6
// baseline (speedup 1.0000x reference)
#include <cuda_runtime.h>
#include <cstdint>

// ---------------------------------------------------------------------------
// TokenRoutedMLP: per-token expert = clip(token_id,0,31999) % 8
//   gu = x @ Wgu[e] ([4096 -> 4096]),  inter = silu(gu[:,:2048]) * gu[:,2048:]
//   out[token] = inter @ Wd[e] ([2048 -> 4096])
// Grouped GEMM via mma.sync m16n8k8 tf32, fp32 accumulation.
// token_ids dtype (int32 vs int64) detected at runtime.
// ---------------------------------------------------------------------------

static constexpr int TOKENS   = 8192;
static constexpr int HID      = 4096;
static constexpr int NEXP     = 8;
static constexpr int INTER    = 2048;
static constexpr int VOCAB    = 32000;
static constexpr int MAXROWS  = 9216;   // 8192 + 8*128 worst-case padding
static constexpr int MAXTILES = 72;     // MAXROWS / 128

// -------------------------- device scratch ---------------------------------
__device__ int   g_is64;
__device__ int   g_cnt[NEXP];
__device__ int   g_cursor[NEXP];
__device__ int   g_tile_expert[MAXTILES];
__device__ int   g_row_token[MAXROWS];
__device__ int   g_total_rows;
__device__ int   g_total_tiles;
__device__ float g_xs[(size_t)MAXROWS * HID];      // sorted+padded x (tf32-rounded)
__device__ float g_gu[(size_t)MAXROWS * HID];      // gemm1 output (fp32)
__device__ float g_inter[(size_t)MAXROWS * INTER]; // silu(g)*u (tf32-rounded)

// ------------------------------ helpers ------------------------------------
__device__ __forceinline__ uint32_t smem_u32(const void* p) {
    uint32_t a;
    asm("{ .reg .u64 t; cvta.to.shared.u64 t, %1; cvt.u32.u64 %0, t; }"
        : "=r"(a) : "l"(p));
    return a;
}
__device__ __forceinline__ uint32_t tf32u(float x) {      // round-to-nearest tf32 bits
    uint32_t u;
    asm("cvt.rna.tf32.f32 %0, %1;" : "=r"(u) : "f"(x));
    return u;
}
__device__ __forceinline__ float tf32r(float x) { return __uint_as_float(tf32u(x)); }
__device__ __forceinline__ void cpa16(uint32_t dst, const void* src) {
    asm volatile("cp.async.cg.shared.global [%0], [%1], 16;" :: "r"(dst), "l"(src));
}
__device__ __forceinline__ int expert_of(long long v) {
    if (v < 0) v = 0;
    if (v > (long long)(VOCAB - 1)) v = VOCAB - 1;
    return (int)(v & 7);
}
__device__ __forceinline__ long long read_id(const void* ids, int i) {
    if (g_is64) return ((const long long*)ids)[i];
    return (long long)((const int*)ids)[i];
}

// ------------------------------ routing ------------------------------------
// Detect int64 vs int32 token_ids: for little-endian int64 values in
// [0, 32000), every odd int32 word (high half) is zero. For an int32 buffer,
// the odd words are random token ids — all-zero with probability ~0.
// Reads 8192 int32 words = 32KB, in-bounds for both layouts.
__global__ void k_detect(const int* __restrict__ idw) {
    __shared__ int s_any;
    if (threadIdx.x == 0) s_any = 0;
    __syncthreads();
    int acc = 0;
    for (int i = threadIdx.x; i < TOKENS / 2; i += blockDim.x)
        acc |= idw[2 * i + 1];
    if (acc) atomicOr(&s_any, 1);
    __syncthreads();
    if (threadIdx.x == 0) g_is64 = (s_any == 0) ? 1 : 0;
}

__global__ void k_init() {
    int gid = blockIdx.x * blockDim.x + threadIdx.x;
    if (gid < NEXP) g_cnt[gid] = 0;
    if (gid < MAXROWS) g_row_token[gid] = -1;
}

__global__ void k_hist(const void* __restrict__ ids) {
    __shared__ int h[NEXP];
    int t = threadIdx.x;
    if (t < NEXP) h[t] = 0;
    __syncthreads();
    int gid = blockIdx.x * blockDim.x + t;
    if (gid < TOKENS) atomicAdd(&h[expert_of(read_id(ids, gid))], 1);
    __syncthreads();
    if (t < NEXP) atomicAdd(&g_cnt[t], h[t]);
}

__global__ void k_plan() {
    int off = 0;
    for (int e = 0; e < NEXP; e++) {
        g_cursor[e] = off;
        int padded = (g_cnt[e] + 127) & ~127;
        int t0 = off >> 7, t1 = (off + padded) >> 7;
        for (int t = t0; t < t1; t++) g_tile_expert[t] = e;
        off += padded;
    }
    g_total_rows  = off;
    g_total_tiles = off >> 7;
}

__global__ void k_scatter(const void* __restrict__ ids) {
    int gid = blockIdx.x * blockDim.x + threadIdx.x;
    if (gid >= TOKENS) return;
    int e = expert_of(read_id(ids, gid));
    int r = atomicAdd(&g_cursor[e], 1);
    g_row_token[r] = gid;
}

__global__ void k_gather(const float* __restrict__ x) {
    int gid = blockIdx.x * blockDim.x + threadIdx.x;   // one float4 each
    int r   = gid >> 10;                               // HID/4 = 1024 per row
    int c4  = gid & 1023;
    if (r >= g_total_rows) return;
    int tok = g_row_token[r];
    float4 v = make_float4(0.f, 0.f, 0.f, 0.f);
    if (tok >= 0) {
        v = *(const float4*)(x + (size_t)tok * HID + c4 * 4);
        v.x = tf32r(v.x); v.y = tf32r(v.y); v.z = tf32r(v.z); v.w = tf32r(v.w);
    }
    *(float4*)(g_xs + (size_t)r * HID + c4 * 4) = v;
}

__global__ void k_swiglu() {
    int gid = blockIdx.x * blockDim.x + threadIdx.x;   // one float4 each
    int r   = gid >> 9;                                // INTER/4 = 512 per row
    int c4  = gid & 511;
    if (r >= g_total_rows) return;
    const float* row = g_gu + (size_t)r * HID;
    float4 g = *(const float4*)(row + c4 * 4);
    float4 u = *(const float4*)(row + INTER + c4 * 4);
    float4 o;
    o.x = tf32r((g.x / (1.f + __expf(-g.x))) * u.x);
    o.y = tf32r((g.y / (1.f + __expf(-g.y))) * u.y);
    o.z = tf32r((g.z / (1.f + __expf(-g.z))) * u.z);
    o.w = tf32r((g.w / (1.f + __expf(-g.w))) * u.w);
    *(float4*)(g_inter + (size_t)r * INTER + c4 * 4) = o;
}

// ------------------------------- GEMM --------------------------------------
// Block: 128(M) x 128(N), K-chunk 32, 256 threads = 8 warps in 2(M) x 4(N).
// Each warp: 64x32 = 4x4 tiles of m16n8k8 tf32 mma.
// SMEM: A [2][128][36] floats, B [2][32][136] floats (conflict-free strides).
// epi==0: A=g_xs   (K=4096), C -> g_gu (row-major, ld 4096)
// epi==1: A=g_inter(K=2048), C -> out[token] via g_row_token
static constexpr int SMEM_BYTES = (2 * 128 * 36 + 2 * 32 * 136) * 4;  // 71680

__global__ __launch_bounds__(256) void gemm_tf32(
    const float* __restrict__ W, float* __restrict__ OutExt, int K, int epi)
{
    int mt = blockIdx.y;
    if (mt >= g_total_tiles) return;
    int nt = blockIdx.x;
    int e  = g_tile_expert[mt];

    const float* A    = (epi == 0) ? g_xs : g_inter;
    float*       Cout = (epi == 0) ? g_gu : OutExt;

    extern __shared__ float sm[];
    float* As_ = sm;             // 2 * 4608 floats
    float* Bs_ = sm + 9216;      // 2 * 4352 floats

    const float* Ag = A + (size_t)mt * 128 * K;
    const float* Bg = W + (size_t)e * K * HID + nt * 128;

    int tid = threadIdx.x;
    int warp = tid >> 5, lane = tid & 31;
    int wm = warp >> 2, wn = warp & 3;
    int grp = lane >> 2, tig = lane & 3;

    float c[4][4][4];
#pragma unroll
    for (int i = 0; i < 4; i++)
#pragma unroll
        for (int j = 0; j < 4; j++)
#pragma unroll
            for (int r = 0; r < 4; r++) c[i][j][r] = 0.f;

    uint32_t sA = smem_u32(As_);
    uint32_t sB = smem_u32(Bs_);

    auto load_stage = [&](int s, int k0) {
#pragma unroll
        for (int it = 0; it < 4; it++) {            // A: 1024 x 16B
            int ch = tid + it * 256;
            int row = ch >> 3, c16 = ch & 7;
            cpa16(sA + s * 18432 + row * 144 + c16 * 16,
                  Ag + (size_t)row * K + k0 + c16 * 4);
        }
#pragma unroll
        for (int it = 0; it < 4; it++) {            // B: 1024 x 16B
            int ch = tid + it * 256;
            int row = ch >> 5, c16 = ch & 31;
            cpa16(sB + s * 17408 + row * 544 + c16 * 16,
                  Bg + (size_t)(k0 + row) * HID + c16 * 4);
        }
        asm volatile("cp.async.commit_group;" ::: "memory");
    };

    int nk = K >> 5;
    load_stage(0, 0);
    for (int kb = 0; kb < nk; kb++) {
        bool more = (kb + 1 < nk);
        if (more) load_stage((kb + 1) & 1, (kb + 1) * 32);
        if (more) asm volatile("cp.async.wait_group 1;" ::: "memory");
        else      asm volatile("cp.async.wait_group 0;" ::: "memory");
        __syncthreads();

        const float* As = As_ + (kb & 1) * 4608;
        const float* Bs = Bs_ + (kb & 1) * 4352;
#pragma unroll
        for (int ks = 0; ks < 4; ks++) {
            int kk = ks * 8;
            uint32_t a[4][4], b[4][2];
#pragma unroll
            for (int i = 0; i < 4; i++) {
                int rA = wm * 64 + i * 16 + grp;
                a[i][0] = __float_as_uint(As[rA * 36 + kk + tig]);
                a[i][1] = __float_as_uint(As[(rA + 8) * 36 + kk + tig]);
                a[i][2] = __float_as_uint(As[rA * 36 + kk + tig + 4]);
                a[i][3] = __float_as_uint(As[(rA + 8) * 36 + kk + tig + 4]);
            }
#pragma unroll
            for (int j = 0; j < 4; j++) {
                int cB = wn * 32 + j * 8 + grp;
                b[j][0] = tf32u(Bs[(kk + tig) * 136 + cB]);
                b[j][1] = tf32u(Bs[(kk + tig + 4) * 136 + cB]);
            }
#pragma unroll
            for (int i = 0; i < 4; i++)
#pragma unroll
                for (int j = 0; j < 4; j++)
                    asm volatile(
                        "mma.sync.aligned.m16n8k8.row.col.f32.tf32.tf32.f32 "
                        "{%0,%1,%2,%3}, {%4,%5,%6,%7}, {%8,%9}, {%0,%1,%2,%3};"
                        : "+f"(c[i][j][0]), "+f"(c[i][j][1]),
                          "+f"(c[i][j][2]), "+f"(c[i][j][3])
                        : "r"(a[i][0]), "r"(a[i][1]), "r"(a[i][2]), "r"(a[i][3]),
                          "r"(b[j][0]), "r"(b[j][1]));
        }
        __syncthreads();
    }

    // epilogue
#pragma unroll
    for (int i = 0; i < 4; i++) {
        int row0 = mt * 128 + wm * 64 + i * 16 + grp;
        int row1 = row0 + 8;
        if (epi == 0) {
#pragma unroll
            for (int j = 0; j < 4; j++) {
                int col = nt * 128 + wn * 32 + j * 8 + tig * 2;
                *(float2*)(Cout + (size_t)row0 * HID + col) =
                    make_float2(c[i][j][0], c[i][j][1]);
                *(float2*)(Cout + (size_t)row1 * HID + col) =
                    make_float2(c[i][j][2], c[i][j][3]);
            }
        } else {
            int t0 = g_row_token[row0];
            int t1 = g_row_token[row1];
#pragma unroll
            for (int j = 0; j < 4; j++) {
                int col = nt * 128 + wn * 32 + j * 8 + tig * 2;
                if (t0 >= 0)
                    *(float2*)(Cout + (size_t)t0 * HID + col) =
                        make_float2(c[i][j][0], c[i][j][1]);
                if (t1 >= 0)
                    *(float2*)(Cout + (size_t)t1 * HID + col) =
                        make_float2(c[i][j][2], c[i][j][3]);
            }
        }
    }
}

// ------------------------------ launch -------------------------------------
extern "C" void kernel_launch(void* const* d_in, const int* in_sizes, int n_in,
                              void* d_out, int out_size) {
    const float* x   = (const float*)d_in[0];
    const void*  ids = d_in[1];                     // int32 or int64, detected
    const float* wgu = (const float*)d_in[2];       // [8][4096][4096]
    const float* wd  = (const float*)d_in[3];       // [8][2048][4096]
    float*       out = (float*)d_out;

    cudaFuncSetAttribute(gemm_tf32,
                         cudaFuncAttributeMaxDynamicSharedMemorySize, SMEM_BYTES);

    k_detect <<<1, 256>>>((const int*)ids);
    k_init   <<<36, 256>>>();                 // 9216 threads
    k_hist   <<<32, 256>>>(ids);
    k_plan   <<<1, 1>>>();
    k_scatter<<<32, 256>>>(ids);
    k_gather <<<36864, 256>>>(x);             // MAXROWS * 1024 float4s

    gemm_tf32<<<dim3(32, MAXTILES), 256, SMEM_BYTES>>>(wgu, nullptr, HID, 0);
    k_swiglu <<<18432, 256>>>();              // MAXROWS * 512 float4s
    gemm_tf32<<<dim3(32, MAXTILES), 256, SMEM_BYTES>>>(wd, out, INTER, 1);
}

// round 8
// speedup vs baseline: 1.0074x; 1.0074x over previous
#include <cuda_runtime.h>
#include <cstdint>

// ---------------------------------------------------------------------------
// TokenRoutedMLP: expert = clip(token_id,0,31999) % 8
//   gu = x @ Wgu[e],  inter = silu(gu[:,:2048]) * gu[:,2048:]
//   out[token] = inter @ Wd[e]
// Grouped GEMM via mma.sync m16n8k8 tf32 (legacy path; tcgen05 PTX rejected by
// this toolchain's .target sm_103). 3-stage cp.async pipeline, 2 CTA/SM,
// SwiGLU fused into GEMM1 epilogue.
// ---------------------------------------------------------------------------

static constexpr int TOKENS   = 8192;
static constexpr int HID      = 4096;
static constexpr int NEXP     = 8;
static constexpr int INTER    = 2048;
static constexpr int VOCAB    = 32000;
static constexpr int MAXROWS  = 9216;   // 8192 + 8*128 worst-case padding
static constexpr int MAXTILES = 72;

// SMEM per stage: A 128x36 floats + B 32x136 floats = 8960 floats
static constexpr int STAGE_FLOATS = 128 * 36 + 32 * 136;     // 8960
static constexpr int A_FLOATS     = 128 * 36;                // 4608
static constexpr int SM3_BYTES    = 3 * STAGE_FLOATS * 4;    // 107520

// -------------------------- device scratch ---------------------------------
__device__ int   g_is64;
__device__ int   g_cnt[NEXP];
__device__ int   g_cursor[NEXP];
__device__ int   g_tile_expert[MAXTILES];
__device__ int   g_row_token[MAXROWS];
__device__ int   g_total_rows;
__device__ int   g_total_tiles;
__device__ float g_xs[(size_t)MAXROWS * HID];      // sorted+padded x (tf32-rounded)
__device__ float g_inter[(size_t)MAXROWS * INTER]; // silu(g)*u (tf32-rounded)

// ------------------------------ helpers ------------------------------------
__device__ __forceinline__ uint32_t smem_u32(const void* p) {
    uint32_t a;
    asm("{ .reg .u64 t; cvta.to.shared.u64 t, %1; cvt.u32.u64 %0, t; }"
        : "=r"(a) : "l"(p));
    return a;
}
__device__ __forceinline__ uint32_t tf32u(float x) {
    uint32_t u;
    asm("cvt.rna.tf32.f32 %0, %1;" : "=r"(u) : "f"(x));
    return u;
}
__device__ __forceinline__ float tf32r(float x) { return __uint_as_float(tf32u(x)); }
__device__ __forceinline__ void cpa16(uint32_t dst, const void* src) {
    asm volatile("cp.async.cg.shared.global [%0], [%1], 16;" :: "r"(dst), "l"(src));
}
__device__ __forceinline__ int expert_of(long long v) {
    if (v < 0) v = 0;
    if (v > (long long)(VOCAB - 1)) v = VOCAB - 1;
    return (int)(v & 7);
}
__device__ __forceinline__ long long read_id(const void* ids, int i) {
    if (g_is64) return ((const long long*)ids)[i];
    return (long long)((const int*)ids)[i];
}

// ------------------------------ routing ------------------------------------
__global__ void k_detect(const int* __restrict__ idw) {
    __shared__ int s_any;
    if (threadIdx.x == 0) s_any = 0;
    __syncthreads();
    int acc = 0;
    for (int i = threadIdx.x; i < TOKENS / 2; i += blockDim.x)
        acc |= idw[2 * i + 1];
    if (acc) atomicOr(&s_any, 1);
    __syncthreads();
    if (threadIdx.x == 0) g_is64 = (s_any == 0) ? 1 : 0;
}

__global__ void k_init() {
    int gid = blockIdx.x * blockDim.x + threadIdx.x;
    if (gid < NEXP) g_cnt[gid] = 0;
    if (gid < MAXROWS) g_row_token[gid] = -1;
}

__global__ void k_hist(const void* __restrict__ ids) {
    __shared__ int h[NEXP];
    int t = threadIdx.x;
    if (t < NEXP) h[t] = 0;
    __syncthreads();
    int gid = blockIdx.x * blockDim.x + t;
    if (gid < TOKENS) atomicAdd(&h[expert_of(read_id(ids, gid))], 1);
    __syncthreads();
    if (t < NEXP) atomicAdd(&g_cnt[t], h[t]);
}

__global__ void k_plan() {
    int off = 0;
    for (int e = 0; e < NEXP; e++) {
        g_cursor[e] = off;
        int padded = (g_cnt[e] + 127) & ~127;
        int t0 = off >> 7, t1 = (off + padded) >> 7;
        for (int t = t0; t < t1; t++) g_tile_expert[t] = e;
        off += padded;
    }
    g_total_rows  = off;
    g_total_tiles = off >> 7;
}

__global__ void k_scatter(const void* __restrict__ ids) {
    int gid = blockIdx.x * blockDim.x + threadIdx.x;
    if (gid >= TOKENS) return;
    int e = expert_of(read_id(ids, gid));
    int r = atomicAdd(&g_cursor[e], 1);
    g_row_token[r] = gid;
}

__global__ void k_gather(const float* __restrict__ x) {
    int gid = blockIdx.x * blockDim.x + threadIdx.x;   // one float4 each
    int r   = gid >> 10;                               // HID/4 = 1024 per row
    int c4  = gid & 1023;
    if (r >= g_total_rows) return;
    int tok = g_row_token[r];
    float4 v = make_float4(0.f, 0.f, 0.f, 0.f);
    if (tok >= 0) {
        v = *(const float4*)(x + (size_t)tok * HID + c4 * 4);
        v.x = tf32r(v.x); v.y = tf32r(v.y); v.z = tf32r(v.z); v.w = tf32r(v.w);
    }
    *(float4*)(g_xs + (size_t)r * HID + c4 * 4) = v;
}

// ------------------------------- GEMM --------------------------------------
// Block tile 128(M) x 128(N), K-chunk 32, 256 threads = 8 warps (2M x 4N),
// each warp 64x32 via 4x4 m16n8k8 tf32 mma. 3-stage cp.async pipeline.
//
// epi==0 (GEMM1): A=g_xs (K=4096), W=[4096][4096] gate|up. Tile N covers
//   64 gate cols (nt*64..) as tile cols 0..63 and 64 up cols (2048+nt*64..)
//   as tile cols 64..127. Epilogue recombines via SMEM and writes
//   silu(g)*u to g_inter (64 cols per CTA). grid.x = 32.
// epi==1 (GEMM2): A=g_inter (K=2048), W=[2048][4096]. Tile cols = nt*128..;
//   epilogue scatters rows to out[token]. grid.x = 32.
__global__ __launch_bounds__(256, 2) void gemm_tf32(
    const float* __restrict__ W, float* __restrict__ OutExt, int K, int epi)
{
    int mt = blockIdx.y;
    if (mt >= g_total_tiles) return;
    int nt = blockIdx.x;
    int e  = g_tile_expert[mt];

    const float* A  = epi ? g_inter : g_xs;
    const float* Ag = A + (size_t)mt * 128 * K;
    const float* We = W + (size_t)e * K * HID;

    extern __shared__ float sm[];

    int tid = threadIdx.x;
    int warp = tid >> 5, lane = tid & 31;
    int wm = warp >> 2, wn = warp & 3;
    int grp = lane >> 2, tig = lane & 3;

    uint32_t sbase = smem_u32(sm);

    // per-thread global column for the B chunk this thread loads (fixed)
    int brow = (tid >> 3) & 31;          // we regroup below; see load_stage
    (void)brow;

    float c[4][4][4];
#pragma unroll
    for (int i = 0; i < 4; i++)
#pragma unroll
        for (int j = 0; j < 4; j++)
#pragma unroll
            for (int r = 0; r < 4; r++) c[i][j][r] = 0.f;

    auto load_stage = [&](int s, int kb) {
        int k0 = kb * 32;
        uint32_t aB = sbase + (uint32_t)(s * STAGE_FLOATS) * 4;
        uint32_t bB = aB + (uint32_t)A_FLOATS * 4;
#pragma unroll
        for (int it = 0; it < 4; it++) {            // A: 128 rows x 8 chunks
            int ch = tid + it * 256;
            int row = ch >> 3, c16 = ch & 7;
            cpa16(aB + row * 144 + c16 * 16,
                  Ag + (size_t)row * K + k0 + c16 * 4);
        }
#pragma unroll
        for (int it = 0; it < 4; it++) {            // B: 32 rows x 32 chunks
            int ch = tid + it * 256;
            int row = ch >> 5, c4 = ch & 31;
            int gcol;
            if (epi == 0)
                gcol = (c4 < 16) ? (nt * 64 + c4 * 4)
                                 : (INTER + nt * 64 + (c4 - 16) * 4);
            else
                gcol = nt * 128 + c4 * 4;
            cpa16(bB + row * 544 + c4 * 16,
                  We + (size_t)(k0 + row) * HID + gcol);
        }
        asm volatile("cp.async.commit_group;" ::: "memory");
    };

    int nk = K >> 5;
    load_stage(0, 0);
    load_stage(1, 1);

    for (int kb = 0; kb < nk; kb++) {
        if (kb + 1 < nk) asm volatile("cp.async.wait_group 1;" ::: "memory");
        else             asm volatile("cp.async.wait_group 0;" ::: "memory");
        __syncthreads();
        if (kb + 2 < nk) load_stage((kb + 2) % 3, kb + 2);

        const float* As = sm + (kb % 3) * STAGE_FLOATS;
        const float* Bs = As + A_FLOATS;
#pragma unroll
        for (int ks = 0; ks < 4; ks++) {
            int kk = ks * 8;
            uint32_t a[4][4], b[4][2];
#pragma unroll
            for (int i = 0; i < 4; i++) {
                int rA = wm * 64 + i * 16 + grp;
                a[i][0] = __float_as_uint(As[rA * 36 + kk + tig]);
                a[i][1] = __float_as_uint(As[(rA + 8) * 36 + kk + tig]);
                a[i][2] = __float_as_uint(As[rA * 36 + kk + tig + 4]);
                a[i][3] = __float_as_uint(As[(rA + 8) * 36 + kk + tig + 4]);
            }
#pragma unroll
            for (int j = 0; j < 4; j++) {
                int cB = wn * 32 + j * 8 + grp;
                b[j][0] = tf32u(Bs[(kk + tig) * 136 + cB]);
                b[j][1] = tf32u(Bs[(kk + tig + 4) * 136 + cB]);
            }
#pragma unroll
            for (int i = 0; i < 4; i++)
#pragma unroll
                for (int j = 0; j < 4; j++)
                    asm volatile(
                        "mma.sync.aligned.m16n8k8.row.col.f32.tf32.tf32.f32 "
                        "{%0,%1,%2,%3}, {%4,%5,%6,%7}, {%8,%9}, {%0,%1,%2,%3};"
                        : "+f"(c[i][j][0]), "+f"(c[i][j][1]),
                          "+f"(c[i][j][2]), "+f"(c[i][j][3])
                        : "r"(a[i][0]), "r"(a[i][1]), "r"(a[i][2]), "r"(a[i][3]),
                          "r"(b[j][0]), "r"(b[j][1]));
        }
    }

    // ------------------------------ epilogue -------------------------------
    if (epi == 0) {
        // stage SMEM is dead; reuse as 128 x 129 accumulator board
        __syncthreads();
        float* ep = sm;
#pragma unroll
        for (int i = 0; i < 4; i++) {
            int r0 = wm * 64 + i * 16 + grp;
#pragma unroll
            for (int j = 0; j < 4; j++) {
                int col = wn * 32 + j * 8 + tig * 2;
                ep[r0 * 129 + col]           = c[i][j][0];
                ep[r0 * 129 + col + 1]       = c[i][j][1];
                ep[(r0 + 8) * 129 + col]     = c[i][j][2];
                ep[(r0 + 8) * 129 + col + 1] = c[i][j][3];
            }
        }
        __syncthreads();
        if (tid < 128) {
            int r = tid;
            float* dst = g_inter + (size_t)(mt * 128 + r) * INTER + nt * 64;
#pragma unroll 4
            for (int cc = 0; cc < 64; cc += 4) {
                float4 o;
                float gv, uv;
                gv = ep[r * 129 + cc];     uv = ep[r * 129 + 64 + cc];
                o.x = tf32r((gv / (1.f + __expf(-gv))) * uv);
                gv = ep[r * 129 + cc + 1]; uv = ep[r * 129 + 64 + cc + 1];
                o.y = tf32r((gv / (1.f + __expf(-gv))) * uv);
                gv = ep[r * 129 + cc + 2]; uv = ep[r * 129 + 64 + cc + 2];
                o.z = tf32r((gv / (1.f + __expf(-gv))) * uv);
                gv = ep[r * 129 + cc + 3]; uv = ep[r * 129 + 64 + cc + 3];
                o.w = tf32r((gv / (1.f + __expf(-gv))) * uv);
                *(float4*)(dst + cc) = o;
            }
        }
    } else {
#pragma unroll
        for (int i = 0; i < 4; i++) {
            int row0 = mt * 128 + wm * 64 + i * 16 + grp;
            int row1 = row0 + 8;
            int t0 = g_row_token[row0];
            int t1 = g_row_token[row1];
#pragma unroll
            for (int j = 0; j < 4; j++) {
                int col = nt * 128 + wn * 32 + j * 8 + tig * 2;
                if (t0 >= 0)
                    *(float2*)(OutExt + (size_t)t0 * HID + col) =
                        make_float2(c[i][j][0], c[i][j][1]);
                if (t1 >= 0)
                    *(float2*)(OutExt + (size_t)t1 * HID + col) =
                        make_float2(c[i][j][2], c[i][j][3]);
            }
        }
    }
}

// ------------------------------ launch -------------------------------------
extern "C" void kernel_launch(void* const* d_in, const int* in_sizes, int n_in,
                              void* d_out, int out_size) {
    const float* x   = (const float*)d_in[0];
    const void*  ids = d_in[1];                    // int32 or int64, detected
    const float* wgu = (const float*)d_in[2];      // [8][4096][4096] (gate|up)
    const float* wd  = (const float*)d_in[3];      // [8][2048][4096]
    float*       out = (float*)d_out;

    cudaFuncSetAttribute(gemm_tf32,
                         cudaFuncAttributeMaxDynamicSharedMemorySize, SM3_BYTES);

    k_detect <<<1, 256>>>((const int*)ids);
    k_init   <<<36, 256>>>();
    k_hist   <<<32, 256>>>(ids);
    k_plan   <<<1, 1>>>();
    k_scatter<<<32, 256>>>(ids);
    k_gather <<<36864, 256>>>(x);

    // GEMM1: 32 n-tiles x 72 m-tiles, fused SwiGLU -> g_inter
    gemm_tf32<<<dim3(32, MAXTILES), 256, SM3_BYTES>>>(wgu, nullptr, HID, 0);
    // GEMM2: 32 n-tiles x 72 m-tiles -> scatter to out
    gemm_tf32<<<dim3(32, MAXTILES), 256, SM3_BYTES>>>(wd, out, INTER, 1);
}